// round 7
// baseline (speedup 1.0000x reference)
#include <cuda_runtime.h>
#include <stdint.h>

#define N_NODES 10000
#define N_EDGES 80000
#define E_TOT   (N_EDGES + N_NODES)   // self-loops appended
#define IN_DIM  768
#define HID     512
#define HEADS   4
#define C1      (HEADS * HID)         // 2048
#define OUT_DIM 768

// ---------------- scratch (static device memory, no allocs) ----------------
__device__ float g_h1[N_NODES * C1];
__device__ float g_out1[N_NODES * C1];
__device__ float g_h2[N_NODES * OUT_DIM];
__device__ float g_as1[N_NODES * HEADS];
__device__ float g_ad1[N_NODES * HEADS];
__device__ float g_emax1[N_NODES * HEADS];
__device__ float g_den1[N_NODES * HEADS];
__device__ float g_ex1[(size_t)E_TOT * HEADS];
__device__ float g_as2[N_NODES];
__device__ float g_ad2[N_NODES];
__device__ float g_emax2[N_NODES];
__device__ float g_den2[N_NODES];
__device__ float g_ex2[E_TOT];
// CSR (edges sorted by dst)
__device__ int g_deg[N_NODES];
__device__ int g_rowptr[N_NODES + 1];
__device__ int g_cur[N_NODES];
__device__ int g_eid[E_TOT];

// ================= TF32x3 tensor-core GEMM (R3, known-good) ================
#define BM 128
#define BN 128
#define BK 32
#define APAD 36
#define BPAD 136

__device__ __forceinline__ uint32_t f2tf32(float x) {
    uint32_t u;
    asm("cvt.rna.tf32.f32 %0, %1;" : "=r"(u) : "f"(x));
    return u;
}

__device__ __forceinline__ void mma_tf32(float c[4],
                                         const uint32_t a[4],
                                         const uint32_t b[2]) {
    asm volatile(
        "mma.sync.aligned.m16n8k8.row.col.f32.tf32.tf32.f32 "
        "{%0,%1,%2,%3},{%4,%5,%6,%7},{%8,%9},{%0,%1,%2,%3};"
        : "+f"(c[0]), "+f"(c[1]), "+f"(c[2]), "+f"(c[3])
        : "r"(a[0]), "r"(a[1]), "r"(a[2]), "r"(a[3]), "r"(b[0]), "r"(b[1]));
}

__device__ __forceinline__ void split_store(float* hi_p, float* lo_p, float4 v) {
    uint32_t hx = f2tf32(v.x), hy = f2tf32(v.y), hz = f2tf32(v.z), hw = f2tf32(v.w);
    float4 hi = make_float4(__uint_as_float(hx), __uint_as_float(hy),
                            __uint_as_float(hz), __uint_as_float(hw));
    float4 lo = make_float4(v.x - hi.x, v.y - hi.y, v.z - hi.z, v.w - hi.w);
    *(float4*)hi_p = hi;
    *(float4*)lo_p = lo;
}

__global__ void gemm_tf32x3(int M, int N, int K,
                            const float* __restrict__ A,
                            const float* __restrict__ B,
                            float* __restrict__ C) {
    extern __shared__ float smem[];
    float* As_hi = smem;
    float* As_lo = As_hi + BM * APAD;
    float* Bs_hi = As_lo + BM * APAD;
    float* Bs_lo = Bs_hi + BK * BPAD;

    const int tid  = threadIdx.x;
    const int lane = tid & 31;
    const int wid  = tid >> 5;
    const int warp_m = (wid >> 2) * 64;
    const int warp_n = (wid & 3) * 32;
    const int brow = blockIdx.y * BM;
    const int bcol = blockIdx.x * BN;

    float acc[4][4][4];
#pragma unroll
    for (int mt = 0; mt < 4; mt++)
#pragma unroll
        for (int nt = 0; nt < 4; nt++)
#pragma unroll
            for (int r = 0; r < 4; r++) acc[mt][nt][r] = 0.f;

    const uint32_t* uAh = (const uint32_t*)As_hi;
    const uint32_t* uAl = (const uint32_t*)As_lo;
    const uint32_t* uBh = (const uint32_t*)Bs_hi;
    const uint32_t* uBl = (const uint32_t*)Bs_lo;

    for (int k0 = 0; k0 < K; k0 += BK) {
#pragma unroll
        for (int p = 0; p < 4; p++) {
            int linear = p * 256 + tid;
            int r  = linear >> 3;
            int kv = (linear & 7) * 4;
            float4 v = (brow + r < M)
                ? *(const float4*)(A + (size_t)(brow + r) * K + k0 + kv)
                : make_float4(0.f, 0.f, 0.f, 0.f);
            split_store(As_hi + r * APAD + kv, As_lo + r * APAD + kv, v);
        }
#pragma unroll
        for (int p = 0; p < 4; p++) {
            int linear = p * 256 + tid;
            int k  = linear >> 5;
            int nv = (linear & 31) * 4;
            float4 v = *(const float4*)(B + (size_t)(k0 + k) * N + bcol + nv);
            split_store(Bs_hi + k * BPAD + nv, Bs_lo + k * BPAD + nv, v);
        }
        __syncthreads();

#pragma unroll
        for (int ks = 0; ks < BK / 8; ks++) {
            uint32_t ah[4][4], al[4][4], bh[4][2], bl[4][2];
            const int kk = ks * 8 + (lane & 3);
#pragma unroll
            for (int mt = 0; mt < 4; mt++) {
                int r = warp_m + mt * 16 + (lane >> 2);
                ah[mt][0] = uAh[r * APAD + kk];
                ah[mt][1] = uAh[(r + 8) * APAD + kk];
                ah[mt][2] = uAh[r * APAD + kk + 4];
                ah[mt][3] = uAh[(r + 8) * APAD + kk + 4];
                al[mt][0] = uAl[r * APAD + kk];
                al[mt][1] = uAl[(r + 8) * APAD + kk];
                al[mt][2] = uAl[r * APAD + kk + 4];
                al[mt][3] = uAl[(r + 8) * APAD + kk + 4];
            }
#pragma unroll
            for (int nt = 0; nt < 4; nt++) {
                int n = warp_n + nt * 8 + (lane >> 2);
                bh[nt][0] = uBh[kk * BPAD + n];
                bh[nt][1] = uBh[(kk + 4) * BPAD + n];
                bl[nt][0] = uBl[kk * BPAD + n];
                bl[nt][1] = uBl[(kk + 4) * BPAD + n];
            }
#pragma unroll
            for (int mt = 0; mt < 4; mt++)
#pragma unroll
                for (int nt = 0; nt < 4; nt++) mma_tf32(acc[mt][nt], ah[mt], bh[nt]);
#pragma unroll
            for (int mt = 0; mt < 4; mt++)
#pragma unroll
                for (int nt = 0; nt < 4; nt++) mma_tf32(acc[mt][nt], ah[mt], bl[nt]);
#pragma unroll
            for (int mt = 0; mt < 4; mt++)
#pragma unroll
                for (int nt = 0; nt < 4; nt++) mma_tf32(acc[mt][nt], al[mt], bh[nt]);
        }
        __syncthreads();
    }

#pragma unroll
    for (int mt = 0; mt < 4; mt++) {
        int r0 = brow + warp_m + mt * 16 + (lane >> 2);
#pragma unroll
        for (int nt = 0; nt < 4; nt++) {
            int cc = bcol + warp_n + nt * 8 + (lane & 3) * 2;
            if (r0 < M)
                *(float2*)&C[(size_t)r0 * N + cc] =
                    make_float2(acc[mt][nt][0], acc[mt][nt][1]);
            if (r0 + 8 < M)
                *(float2*)&C[(size_t)(r0 + 8) * N + cc] =
                    make_float2(acc[mt][nt][2], acc[mt][nt][3]);
        }
    }
}

#define GEMM_SMEM ((2 * BM * APAD + 2 * BK * BPAD) * 4)

// ----------------- per-node attention coefficients -------------------------
__global__ void attn_coef(const float* __restrict__ h,
                          const float* __restrict__ a_src,
                          const float* __restrict__ a_dst,
                          float* __restrict__ as_out,
                          float* __restrict__ ad_out,
                          int H, int D) {
    int n = blockIdx.x;
    int w = threadIdx.x >> 5;
    int lane = threadIdx.x & 31;
    const float* hp  = h + (size_t)n * H * D + (size_t)w * D;
    const float* ap  = a_src + (size_t)w * D;
    const float* bp  = a_dst + (size_t)w * D;
    float s = 0.f, d = 0.f;
    for (int i = lane; i < D; i += 32) {
        float v = hp[i];
        s += v * ap[i];
        d += v * bp[i];
    }
#pragma unroll
    for (int off = 16; off; off >>= 1) {
        s += __shfl_down_sync(0xffffffffu, s, off);
        d += __shfl_down_sync(0xffffffffu, d, off);
    }
    if (lane == 0) {
        as_out[(size_t)n * H + w] = s;
        ad_out[(size_t)n * H + w] = d;
    }
}

// ----------------- softmax init --------------------------------------------
__global__ void init_softmax(float* __restrict__ emax, float* __restrict__ den, int n) {
    int i = blockIdx.x * blockDim.x + threadIdx.x;
    if (i < n) {
        emax[i] = __int_as_float(0xff800000u);
        den[i]  = 0.f;
    }
}

__device__ __forceinline__ void atomicMaxFloat(float* addr, float val) {
    if (val >= 0.f)
        atomicMax((int*)addr, __float_as_int(val));
    else
        atomicMin((unsigned int*)addr, __float_as_uint(val));
}

// edge_index is int32 (JAX x64 disabled). [2,E] row-major.
__device__ __forceinline__ void edge_ends(const int* __restrict__ ei,
                                          int e, int E, int& src, int& dst) {
    if (e < E) {
        src = min(max(ei[e], 0), N_NODES - 1);
        dst = min(max(ei[E + e], 0), N_NODES - 1);
    } else {
        src = dst = e - E;
    }
}

__global__ void edge_max(const int* __restrict__ ei, int E, int Etot, int H,
                         const float* __restrict__ asn, const float* __restrict__ adn,
                         float* __restrict__ emax) {
    int idx = blockIdx.x * blockDim.x + threadIdx.x;
    if (idx >= Etot * H) return;
    int e = idx / H, hh = idx - e * H;
    int src, dst;
    edge_ends(ei, e, E, src, dst);
    float v = asn[(size_t)src * H + hh] + adn[(size_t)dst * H + hh];
    v = v > 0.f ? v : 0.2f * v;
    atomicMaxFloat(&emax[(size_t)dst * H + hh], v);
}

__global__ void edge_exp(const int* __restrict__ ei, int E, int Etot, int H,
                         const float* __restrict__ asn, const float* __restrict__ adn,
                         const float* __restrict__ emax,
                         float* __restrict__ ex, float* __restrict__ den) {
    int idx = blockIdx.x * blockDim.x + threadIdx.x;
    if (idx >= Etot * H) return;
    int e = idx / H, hh = idx - e * H;
    int src, dst;
    edge_ends(ei, e, E, src, dst);
    float v = asn[(size_t)src * H + hh] + adn[(size_t)dst * H + hh];
    v = v > 0.f ? v : 0.2f * v;
    float xv = __expf(v - emax[(size_t)dst * H + hh]);
    ex[idx] = xv;
    atomicAdd(&den[(size_t)dst * H + hh], xv);
}

// alpha = ex / (den[dst]+eps), in place
__global__ void edge_alpha(const int* __restrict__ ei, int E, int Etot, int H,
                           const float* __restrict__ den, float* __restrict__ ex) {
    int idx = blockIdx.x * blockDim.x + threadIdx.x;
    if (idx >= Etot * H) return;
    int e = idx / H, hh = idx - e * H;
    int src, dst;
    edge_ends(ei, e, E, src, dst);
    ex[idx] = ex[idx] / (den[(size_t)dst * H + hh] + 1e-16f);
}

// ----------------- CSR build ------------------------------------------------
__global__ void csr_count(const int* __restrict__ ei, int* __restrict__ deg) {
    int e = blockIdx.x * blockDim.x + threadIdx.x;
    if (e >= E_TOT) return;
    int src, dst;
    edge_ends(ei, e, N_EDGES, src, dst);
    atomicAdd(&deg[dst], 1);
}

__global__ void csr_scan(const int* __restrict__ deg,
                         int* __restrict__ row_ptr, int* __restrict__ cur) {
    __shared__ int s[1024];
    __shared__ int carry;
    if (threadIdx.x == 0) carry = 0;
    __syncthreads();
    for (int base = 0; base < N_NODES; base += 1024) {
        int i = base + (int)threadIdx.x;
        int v = (i < N_NODES) ? deg[i] : 0;
        s[threadIdx.x] = v;
        __syncthreads();
        for (int off = 1; off < 1024; off <<= 1) {
            int t = (threadIdx.x >= off) ? s[threadIdx.x - off] : 0;
            __syncthreads();
            s[threadIdx.x] += t;
            __syncthreads();
        }
        int exc = carry + s[threadIdx.x] - v;
        if (i < N_NODES) { row_ptr[i] = exc; cur[i] = exc; }
        __syncthreads();
        if (threadIdx.x == 1023) carry += s[1023];
        __syncthreads();
    }
    if (threadIdx.x == 0) row_ptr[N_NODES] = E_TOT;
}

__global__ void csr_scatter(const int* __restrict__ ei,
                            int* __restrict__ cur, int* __restrict__ eid) {
    int e = blockIdx.x * blockDim.x + threadIdx.x;
    if (e >= E_TOT) return;
    int src, dst;
    edge_ends(ei, e, N_EDGES, src, dst);
    int pos = atomicAdd(&cur[dst], 1);
    eid[pos] = e;
}

// ----------------- CSR gather aggregation (fused bias/act) ------------------
// grid = N_NODES, blockDim = H*Dh/4. alpha precomputed per (edge, head).
__global__ void gat_gather(const int* __restrict__ ei,
                           const int* __restrict__ row_ptr,
                           const int* __restrict__ eid,
                           const float* __restrict__ h,
                           const float* __restrict__ alpha,
                           const float* __restrict__ bias,
                           float* __restrict__ out,
                           int H, int Dh, int do_elu) {
    const int n = blockIdx.x;
    const int cols = H * Dh;
    const int d = threadIdx.x * 4;
    const int hh = d / Dh;
    float4 acc = make_float4(0.f, 0.f, 0.f, 0.f);
    const int rp0 = row_ptr[n], rp1 = row_ptr[n + 1];
    for (int j = rp0; j < rp1; j++) {
        int e = eid[j];
        int src = (e < N_EDGES) ? min(max(ei[e], 0), N_NODES - 1) : e - N_EDGES;
        float a = alpha[(size_t)e * H + hh];
        float4 v = *(const float4*)(h + (size_t)src * cols + d);
        acc.x += a * v.x;
        acc.y += a * v.y;
        acc.z += a * v.z;
        acc.w += a * v.w;
    }
    float4 b4 = *(const float4*)(bias + d);
    acc.x += b4.x; acc.y += b4.y; acc.z += b4.z; acc.w += b4.w;
    if (do_elu) {
        acc.x = acc.x > 0.f ? acc.x : expm1f(acc.x);
        acc.y = acc.y > 0.f ? acc.y : expm1f(acc.y);
        acc.z = acc.z > 0.f ? acc.z : expm1f(acc.z);
        acc.w = acc.w > 0.f ? acc.w : expm1f(acc.w);
    }
    *(float4*)(out + (size_t)n * cols + d) = acc;
}

// ---------------------------------------------------------------------------
extern "C" void kernel_launch(void* const* d_in, const int* in_sizes, int n_in,
                              void* d_out, int out_size) {
    const float* x   = (const float*)d_in[0];
    const int*   ei  = (const int*)d_in[1];
    const float* W1  = (const float*)d_in[2];
    const float* a1s = (const float*)d_in[3];
    const float* a1d = (const float*)d_in[4];
    const float* b1  = (const float*)d_in[5];
    const float* W2  = (const float*)d_in[6];
    const float* a2s = (const float*)d_in[7];
    const float* a2d = (const float*)d_in[8];
    const float* b2  = (const float*)d_in[9];
    float*       out = (float*)d_out;

    float *h1, *out1, *h2, *as1, *ad1, *em1, *dn1, *ex1;
    float *as2, *ad2, *em2, *dn2, *ex2;
    int *deg, *rowptr, *cur, *eid;
    cudaGetSymbolAddress((void**)&h1,  g_h1);
    cudaGetSymbolAddress((void**)&out1, g_out1);
    cudaGetSymbolAddress((void**)&h2,  g_h2);
    cudaGetSymbolAddress((void**)&as1, g_as1);
    cudaGetSymbolAddress((void**)&ad1, g_ad1);
    cudaGetSymbolAddress((void**)&em1, g_emax1);
    cudaGetSymbolAddress((void**)&dn1, g_den1);
    cudaGetSymbolAddress((void**)&ex1, g_ex1);
    cudaGetSymbolAddress((void**)&as2, g_as2);
    cudaGetSymbolAddress((void**)&ad2, g_ad2);
    cudaGetSymbolAddress((void**)&em2, g_emax2);
    cudaGetSymbolAddress((void**)&dn2, g_den2);
    cudaGetSymbolAddress((void**)&ex2, g_ex2);
    cudaGetSymbolAddress((void**)&deg,    g_deg);
    cudaGetSymbolAddress((void**)&rowptr, g_rowptr);
    cudaGetSymbolAddress((void**)&cur,    g_cur);
    cudaGetSymbolAddress((void**)&eid,    g_eid);

    cudaFuncSetAttribute(gemm_tf32x3,
                         cudaFuncAttributeMaxDynamicSharedMemorySize, GEMM_SMEM);

    // ---- CSR build (graph shared by both layers) ----
    cudaMemsetAsync(deg, 0, sizeof(int) * N_NODES);
    csr_count<<<(E_TOT + 255) / 256, 256>>>(ei, deg);
    csr_scan<<<1, 1024>>>(deg, rowptr, cur);
    csr_scatter<<<(E_TOT + 255) / 256, 256>>>(ei, cur, eid);

    // ---------------- layer 1 ----------------
    {
        dim3 grid(C1 / 128, (N_NODES + 127) / 128);
        gemm_tf32x3<<<grid, 256, GEMM_SMEM>>>(N_NODES, C1, IN_DIM, x, W1, h1);
    }
    attn_coef<<<N_NODES, 32 * HEADS>>>(h1, a1s, a1d, as1, ad1, HEADS, HID);

    int tot1 = N_NODES * HEADS;
    init_softmax<<<(tot1 + 255) / 256, 256>>>(em1, dn1, tot1);

    int et1 = E_TOT * HEADS;
    edge_max<<<(et1 + 255) / 256, 256>>>(ei, N_EDGES, E_TOT, HEADS, as1, ad1, em1);
    edge_exp<<<(et1 + 255) / 256, 256>>>(ei, N_EDGES, E_TOT, HEADS, as1, ad1, em1, ex1, dn1);
    edge_alpha<<<(et1 + 255) / 256, 256>>>(ei, N_EDGES, E_TOT, HEADS, dn1, ex1);
    gat_gather<<<N_NODES, C1 / 4>>>(ei, rowptr, eid, h1, ex1, b1, out1, HEADS, HID, 1);

    // ---------------- layer 2 ----------------
    {
        dim3 grid(OUT_DIM / 128, (N_NODES + 127) / 128);
        gemm_tf32x3<<<grid, 256, GEMM_SMEM>>>(N_NODES, OUT_DIM, C1, out1, W2, h2);
    }
    attn_coef<<<N_NODES, 32>>>(h2, a2s, a2d, as2, ad2, 1, OUT_DIM);

    init_softmax<<<(N_NODES + 255) / 256, 256>>>(em2, dn2, N_NODES);

    edge_max<<<(E_TOT + 255) / 256, 256>>>(ei, N_EDGES, E_TOT, 1, as2, ad2, em2);
    edge_exp<<<(E_TOT + 255) / 256, 256>>>(ei, N_EDGES, E_TOT, 1, as2, ad2, em2, ex2, dn2);
    edge_alpha<<<(E_TOT + 255) / 256, 256>>>(ei, N_EDGES, E_TOT, 1, dn2, ex2);
    gat_gather<<<N_NODES, OUT_DIM / 4>>>(ei, rowptr, eid, h2, ex2, b2, out, 1, OUT_DIM, 0);
}

// round 8
// speedup vs baseline: 1.3632x; 1.3632x over previous
#include <cuda_runtime.h>
#include <stdint.h>

#define N_NODES 10000
#define N_EDGES 80000
#define E_TOT   (N_EDGES + N_NODES)   // self-loops appended
#define IN_DIM  768
#define HID     512
#define HEADS   4
#define C1      (HEADS * HID)         // 2048
#define OUT_DIM 768

// ---------------- scratch (static device memory, no allocs) ----------------
__device__ float g_h1[N_NODES * C1];
__device__ float g_out1[N_NODES * C1];
__device__ float g_h2[N_NODES * OUT_DIM];
__device__ float g_as1[N_NODES * HEADS];
__device__ float g_ad1[N_NODES * HEADS];
__device__ float g_emax1[N_NODES * HEADS];
__device__ float g_den1[N_NODES * HEADS];
__device__ float g_ex1[(size_t)E_TOT * HEADS];
__device__ float g_as2[N_NODES];
__device__ float g_ad2[N_NODES];
__device__ float g_emax2[N_NODES];
__device__ float g_den2[N_NODES];
__device__ float g_ex2[E_TOT];

// ================= BF16x3 tensor-core GEMM =================================
// C[M,N] = A[M,K] @ B[K,N] row-major.  Split fp32 = bf16_hi + bf16_lo (exact
// residual); D += Ah*Bh + Ah*Bl + Al*Bh with fp32 accumulation.
// Block 128x128x32, 256 threads (8 warps, 2x4), warp tile 64x32.
// Smem holds packed bf16x2 pairs along k:  A: [128][16] pairs (+pad),
// B: [16][128] pairs (+pad), pair p = (k=2p low half, k=2p+1 high half).
#define BM 128
#define BN 128
#define BK 32
#define KP (BK / 2)      // 16 k-pairs
#define APADP 20         // 16+4 uint32 per A row  -> conflict-free frags
#define BPADP 136        // 128+8 uint32 per B row -> conflict-free frags

// pack two fp32 into bf16x2: low half = lo element (k), high half = hi (k+1)
__device__ __forceinline__ uint32_t pack_bf16x2(float e_lo, float e_hi) {
    uint32_t r;
    asm("cvt.rn.bf16x2.f32 %0, %1, %2;" : "=r"(r) : "f"(e_hi), "f"(e_lo));
    return r;
}

__device__ __forceinline__ void mma_bf16(float c[4],
                                         const uint32_t a[4],
                                         const uint32_t b[2]) {
    asm volatile(
        "mma.sync.aligned.m16n8k16.row.col.f32.bf16.bf16.f32 "
        "{%0,%1,%2,%3},{%4,%5,%6,%7},{%8,%9},{%0,%1,%2,%3};"
        : "+f"(c[0]), "+f"(c[1]), "+f"(c[2]), "+f"(c[3])
        : "r"(a[0]), "r"(a[1]), "r"(a[2]), "r"(a[3]), "r"(b[0]), "r"(b[1]));
}

// split a pair of fp32 into hi bf16x2 and lo (residual) bf16x2
__device__ __forceinline__ void split_pair(float x, float y,
                                           uint32_t& hi, uint32_t& lo) {
    hi = pack_bf16x2(x, y);
    float hx = __uint_as_float(hi << 16);
    float hy = __uint_as_float(hi & 0xffff0000u);
    lo = pack_bf16x2(x - hx, y - hy);
}

__global__ void __launch_bounds__(256)
gemm_bf16x3(int M, int N, int K,
            const float* __restrict__ A,
            const float* __restrict__ B,
            float* __restrict__ C) {
    __shared__ uint32_t sAh[BM * APADP];
    __shared__ uint32_t sAl[BM * APADP];
    __shared__ uint32_t sBh[KP * BPADP];
    __shared__ uint32_t sBl[KP * BPADP];

    const int tid  = threadIdx.x;
    const int lane = tid & 31;
    const int wid  = tid >> 5;
    const int warp_m = (wid >> 2) * 64;
    const int warp_n = (wid & 3) * 32;
    const int brow = blockIdx.y * BM;
    const int bcol = blockIdx.x * BN;

    float acc[4][4][4];
#pragma unroll
    for (int mt = 0; mt < 4; mt++)
#pragma unroll
        for (int nt = 0; nt < 4; nt++)
#pragma unroll
            for (int r = 0; r < 4; r++) acc[mt][nt][r] = 0.f;

    for (int k0 = 0; k0 < K; k0 += BK) {
        // ---- A tile 128x32: 4 passes, thread -> float4 at (r, kv) ----
#pragma unroll
        for (int p = 0; p < 4; p++) {
            int linear = p * 256 + tid;
            int r  = linear >> 3;
            int kv = (linear & 7) * 4;
            float4 v = (brow + r < M)
                ? *(const float4*)(A + (size_t)(brow + r) * K + k0 + kv)
                : make_float4(0.f, 0.f, 0.f, 0.f);
            uint32_t h0, l0, h1, l1;
            split_pair(v.x, v.y, h0, l0);
            split_pair(v.z, v.w, h1, l1);
            int o = r * APADP + (kv >> 1);
            *(uint2*)&sAh[o] = make_uint2(h0, h1);
            *(uint2*)&sAl[o] = make_uint2(l0, l1);
        }
        // ---- B tile 32x128: 2 passes, thread -> (k, nv) and (k+1, nv) ----
#pragma unroll
        for (int p = 0; p < 2; p++) {
            int linear = p * 256 + tid;
            int kp = linear >> 5;            // 0..15
            int nv = (linear & 31) * 4;
            const float* b0 = B + (size_t)(k0 + 2 * kp) * N + bcol + nv;
            float4 v0 = *(const float4*)b0;
            float4 v1 = *(const float4*)(b0 + N);
            uint32_t hh[4], ll[4];
            split_pair(v0.x, v1.x, hh[0], ll[0]);
            split_pair(v0.y, v1.y, hh[1], ll[1]);
            split_pair(v0.z, v1.z, hh[2], ll[2]);
            split_pair(v0.w, v1.w, hh[3], ll[3]);
            int o = kp * BPADP + nv;
            *(uint4*)&sBh[o] = make_uint4(hh[0], hh[1], hh[2], hh[3]);
            *(uint4*)&sBl[o] = make_uint4(ll[0], ll[1], ll[2], ll[3]);
        }
        __syncthreads();

#pragma unroll
        for (int ks = 0; ks < BK / 16; ks++) {
            uint32_t ah[4][4], al[4][4], bh[4][2], bl[4][2];
            const int cc = ks * 8 + (lane & 3);   // k-pair index
#pragma unroll
            for (int mt = 0; mt < 4; mt++) {
                int r = warp_m + mt * 16 + (lane >> 2);
                ah[mt][0] = sAh[r * APADP + cc];
                ah[mt][1] = sAh[(r + 8) * APADP + cc];
                ah[mt][2] = sAh[r * APADP + cc + 4];
                ah[mt][3] = sAh[(r + 8) * APADP + cc + 4];
                al[mt][0] = sAl[r * APADP + cc];
                al[mt][1] = sAl[(r + 8) * APADP + cc];
                al[mt][2] = sAl[r * APADP + cc + 4];
                al[mt][3] = sAl[(r + 8) * APADP + cc + 4];
            }
#pragma unroll
            for (int nt = 0; nt < 4; nt++) {
                int n = warp_n + nt * 8 + (lane >> 2);
                bh[nt][0] = sBh[cc * BPADP + n];
                bh[nt][1] = sBh[(cc + 4) * BPADP + n];
                bl[nt][0] = sBl[cc * BPADP + n];
                bl[nt][1] = sBl[(cc + 4) * BPADP + n];
            }
            // hi*hi ; hi*lo ; lo*hi  (dependent mmas 16 issues apart)
#pragma unroll
            for (int mt = 0; mt < 4; mt++)
#pragma unroll
                for (int nt = 0; nt < 4; nt++) mma_bf16(acc[mt][nt], ah[mt], bh[nt]);
#pragma unroll
            for (int mt = 0; mt < 4; mt++)
#pragma unroll
                for (int nt = 0; nt < 4; nt++) mma_bf16(acc[mt][nt], ah[mt], bl[nt]);
#pragma unroll
            for (int mt = 0; mt < 4; mt++)
#pragma unroll
                for (int nt = 0; nt < 4; nt++) mma_bf16(acc[mt][nt], al[mt], bh[nt]);
        }
        __syncthreads();
    }

    // ---- epilogue (same acc layout as m16n8 fp32) ----
#pragma unroll
    for (int mt = 0; mt < 4; mt++) {
        int r0 = brow + warp_m + mt * 16 + (lane >> 2);
#pragma unroll
        for (int nt = 0; nt < 4; nt++) {
            int cc = bcol + warp_n + nt * 8 + (lane & 3) * 2;
            if (r0 < M)
                *(float2*)&C[(size_t)r0 * N + cc] =
                    make_float2(acc[mt][nt][0], acc[mt][nt][1]);
            if (r0 + 8 < M)
                *(float2*)&C[(size_t)(r0 + 8) * N + cc] =
                    make_float2(acc[mt][nt][2], acc[mt][nt][3]);
        }
    }
}

// ----------------- per-node attention coefficients -------------------------
__global__ void attn_coef(const float* __restrict__ h,
                          const float* __restrict__ a_src,
                          const float* __restrict__ a_dst,
                          float* __restrict__ as_out,
                          float* __restrict__ ad_out,
                          int H, int D) {
    int n = blockIdx.x;
    int w = threadIdx.x >> 5;
    int lane = threadIdx.x & 31;
    const float* hp  = h + (size_t)n * H * D + (size_t)w * D;
    const float* ap  = a_src + (size_t)w * D;
    const float* bp  = a_dst + (size_t)w * D;
    float s = 0.f, d = 0.f;
    for (int i = lane; i < D; i += 32) {
        float v = hp[i];
        s += v * ap[i];
        d += v * bp[i];
    }
#pragma unroll
    for (int off = 16; off; off >>= 1) {
        s += __shfl_down_sync(0xffffffffu, s, off);
        d += __shfl_down_sync(0xffffffffu, d, off);
    }
    if (lane == 0) {
        as_out[(size_t)n * H + w] = s;
        ad_out[(size_t)n * H + w] = d;
    }
}

// ----------------- softmax init --------------------------------------------
__global__ void init_softmax(float* __restrict__ emax, float* __restrict__ den, int n) {
    int i = blockIdx.x * blockDim.x + threadIdx.x;
    if (i < n) {
        emax[i] = __int_as_float(0xff800000u);
        den[i]  = 0.f;
    }
}

__device__ __forceinline__ void atomicMaxFloat(float* addr, float val) {
    if (val >= 0.f)
        atomicMax((int*)addr, __float_as_int(val));
    else
        atomicMin((unsigned int*)addr, __float_as_uint(val));
}

// edge_index is int32 (JAX x64 disabled). [2,E] row-major.
__device__ __forceinline__ void edge_ends(const int* __restrict__ ei,
                                          int e, int E, int& src, int& dst) {
    if (e < E) {
        src = min(max(ei[e], 0), N_NODES - 1);
        dst = min(max(ei[E + e], 0), N_NODES - 1);
    } else {
        src = dst = e - E;
    }
}

__global__ void edge_max(const int* __restrict__ ei, int E, int Etot, int H,
                         const float* __restrict__ asn, const float* __restrict__ adn,
                         float* __restrict__ emax) {
    int idx = blockIdx.x * blockDim.x + threadIdx.x;
    if (idx >= Etot * H) return;
    int e = idx / H, hh = idx - e * H;
    int src, dst;
    edge_ends(ei, e, E, src, dst);
    float v = asn[(size_t)src * H + hh] + adn[(size_t)dst * H + hh];
    v = v > 0.f ? v : 0.2f * v;
    atomicMaxFloat(&emax[(size_t)dst * H + hh], v);
}

__global__ void edge_exp(const int* __restrict__ ei, int E, int Etot, int H,
                         const float* __restrict__ asn, const float* __restrict__ adn,
                         const float* __restrict__ emax,
                         float* __restrict__ ex, float* __restrict__ den) {
    int idx = blockIdx.x * blockDim.x + threadIdx.x;
    if (idx >= Etot * H) return;
    int e = idx / H, hh = idx - e * H;
    int src, dst;
    edge_ends(ei, e, E, src, dst);
    float v = asn[(size_t)src * H + hh] + adn[(size_t)dst * H + hh];
    v = v > 0.f ? v : 0.2f * v;
    float xv = __expf(v - emax[(size_t)dst * H + hh]);
    ex[idx] = xv;
    atomicAdd(&den[(size_t)dst * H + hh], xv);
}

__global__ void aggregate(const int* __restrict__ ei, int E,
                          const float* __restrict__ h,
                          const float* __restrict__ ex,
                          const float* __restrict__ den,
                          float* __restrict__ out, int H, int Dh) {
    int e = blockIdx.x;
    int src, dst;
    edge_ends(ei, e, E, src, dst);
    int cols = H * Dh;
    int d = threadIdx.x * 4;
    int hh = d / Dh;
    float alpha = ex[(size_t)e * H + hh] / (den[(size_t)dst * H + hh] + 1e-16f);
    float4 v = *(const float4*)(h + (size_t)src * cols + d);
    float* o = out + (size_t)dst * cols + d;
    atomicAdd(o + 0, alpha * v.x);
    atomicAdd(o + 1, alpha * v.y);
    atomicAdd(o + 2, alpha * v.z);
    atomicAdd(o + 3, alpha * v.w);
}

__global__ void elu_bias(float* __restrict__ x, const float* __restrict__ b,
                         int n, int cols) {
    int i = blockIdx.x * blockDim.x + threadIdx.x;
    if (i >= n) return;
    float v = x[i] + b[i % cols];
    x[i] = v > 0.f ? v : expm1f(v);
}

__global__ void add_bias(float* __restrict__ x, const float* __restrict__ b,
                         int n, int cols) {
    int i = blockIdx.x * blockDim.x + threadIdx.x;
    if (i >= n) return;
    x[i] += b[i % cols];
}

// ---------------------------------------------------------------------------
extern "C" void kernel_launch(void* const* d_in, const int* in_sizes, int n_in,
                              void* d_out, int out_size) {
    const float* x   = (const float*)d_in[0];
    const int*   ei  = (const int*)d_in[1];     // int32 (JAX x64 disabled)
    const float* W1  = (const float*)d_in[2];
    const float* a1s = (const float*)d_in[3];
    const float* a1d = (const float*)d_in[4];
    const float* b1  = (const float*)d_in[5];
    const float* W2  = (const float*)d_in[6];
    const float* a2s = (const float*)d_in[7];
    const float* a2d = (const float*)d_in[8];
    const float* b2  = (const float*)d_in[9];
    float*       out = (float*)d_out;

    float *h1, *out1, *h2, *as1, *ad1, *em1, *dn1, *ex1;
    float *as2, *ad2, *em2, *dn2, *ex2;
    cudaGetSymbolAddress((void**)&h1,  g_h1);
    cudaGetSymbolAddress((void**)&out1, g_out1);
    cudaGetSymbolAddress((void**)&h2,  g_h2);
    cudaGetSymbolAddress((void**)&as1, g_as1);
    cudaGetSymbolAddress((void**)&ad1, g_ad1);
    cudaGetSymbolAddress((void**)&em1, g_emax1);
    cudaGetSymbolAddress((void**)&dn1, g_den1);
    cudaGetSymbolAddress((void**)&ex1, g_ex1);
    cudaGetSymbolAddress((void**)&as2, g_as2);
    cudaGetSymbolAddress((void**)&ad2, g_ad2);
    cudaGetSymbolAddress((void**)&em2, g_emax2);
    cudaGetSymbolAddress((void**)&dn2, g_den2);
    cudaGetSymbolAddress((void**)&ex2, g_ex2);

    // ---------------- layer 1 ----------------
    {
        dim3 grid(C1 / 128, (N_NODES + 127) / 128);
        gemm_bf16x3<<<grid, 256>>>(N_NODES, C1, IN_DIM, x, W1, h1);
    }
    attn_coef<<<N_NODES, 32 * HEADS>>>(h1, a1s, a1d, as1, ad1, HEADS, HID);

    int tot1 = N_NODES * HEADS;
    init_softmax<<<(tot1 + 255) / 256, 256>>>(em1, dn1, tot1);
    cudaMemsetAsync(out1, 0, sizeof(float) * (size_t)N_NODES * C1);

    int et1 = E_TOT * HEADS;
    edge_max<<<(et1 + 255) / 256, 256>>>(ei, N_EDGES, E_TOT, HEADS, as1, ad1, em1);
    edge_exp<<<(et1 + 255) / 256, 256>>>(ei, N_EDGES, E_TOT, HEADS, as1, ad1, em1, ex1, dn1);
    aggregate<<<E_TOT, C1 / 4>>>(ei, N_EDGES, h1, ex1, dn1, out1, HEADS, HID);

    int n1 = N_NODES * C1;
    elu_bias<<<(n1 + 255) / 256, 256>>>(out1, b1, n1, C1);

    // ---------------- layer 2 ----------------
    {
        dim3 grid(OUT_DIM / 128, (N_NODES + 127) / 128);
        gemm_bf16x3<<<grid, 256>>>(N_NODES, OUT_DIM, C1, out1, W2, h2);
    }
    attn_coef<<<N_NODES, 32>>>(h2, a2s, a2d, as2, ad2, 1, OUT_DIM);

    init_softmax<<<(N_NODES + 255) / 256, 256>>>(em2, dn2, N_NODES);
    cudaMemsetAsync(out, 0, sizeof(float) * (size_t)N_NODES * OUT_DIM);

    edge_max<<<(E_TOT + 255) / 256, 256>>>(ei, N_EDGES, E_TOT, 1, as2, ad2, em2);
    edge_exp<<<(E_TOT + 255) / 256, 256>>>(ei, N_EDGES, E_TOT, 1, as2, ad2, em2, ex2, dn2);
    aggregate<<<E_TOT, OUT_DIM / 4>>>(ei, N_EDGES, h2, ex2, dn2, out, 1, OUT_DIM);

    int n2 = N_NODES * OUT_DIM;
    add_bias<<<(n2 + 255) / 256, 256>>>(out, b2, n2, OUT_DIM);
}